// round 1
// baseline (speedup 1.0000x reference)
#include <cuda_runtime.h>
#include <cstdint>

// ============================================================================
// RPN GT matcher — bit-exact JAX Threefry reproduction + integer-monotone
// shortcuts for gumbel/uniform ordering.
// ============================================================================

#define N_ANCH 262144
#define NB 4
#define NG 64
#define TFG 153          // TARGET_FG
#define SB 512           // SAMPLE_BATCH
#define FULLMASK 0xFFFFFFFFu

// JAX PRNG mode: 1 = jax_threefry_partitionable (modern default),
//                0 = legacy threefry counter layout.
#define JAX_PARTITIONABLE 1

struct Keys { uint32_t kp0[NB], kp1[NB], kn0[NB], kn1[NB]; };

__host__ __device__ __forceinline__ uint32_t rotl32(uint32_t x, int r) {
#ifdef __CUDA_ARCH__
    return __funnelshift_l(x, x, r);
#else
    return (x << r) | (x >> (32 - r));
#endif
}

// Threefry-2x32, 20 rounds, exactly as jax._src.prng.threefry2x32
__host__ __device__ __forceinline__ void threefry(uint32_t k0, uint32_t k1,
                                                  uint32_t x0, uint32_t x1,
                                                  uint32_t& o0, uint32_t& o1) {
    uint32_t ks2 = k0 ^ k1 ^ 0x1BD11BDAu;
    x0 += k0; x1 += k1;
#define TFR(r) { x0 += x1; x1 = rotl32(x1, r); x1 ^= x0; }
    TFR(13) TFR(15) TFR(26) TFR(6)
    x0 += k1;  x1 += ks2 + 1u;
    TFR(17) TFR(29) TFR(16) TFR(24)
    x0 += ks2; x1 += k0 + 2u;
    TFR(13) TFR(15) TFR(26) TFR(6)
    x0 += k0;  x1 += k1 + 3u;
    TFR(17) TFR(29) TFR(16) TFR(24)
    x0 += k1;  x1 += ks2 + 4u;
    TFR(13) TFR(15) TFR(26) TFR(6)
    x0 += ks2; x1 += k0 + 5u;
#undef TFR
    o0 = x0; o1 = x1;
}

// 32-bit random word at flat index idx of a random_bits stream of (even) size
// 2*half. Partitionable: counter (0, idx), out = o0 ^ o1.
// Original: blocks j pair positions (j, j+half); o0 -> j, o1 -> j+half.
__device__ __forceinline__ uint32_t rbits(uint32_t k0, uint32_t k1,
                                          uint32_t idx, uint32_t half) {
#if JAX_PARTITIONABLE
    (void)half;
    uint32_t a, b; threefry(k0, k1, 0u, idx, a, b);
    return a ^ b;
#else
    uint32_t a, b;
    if (idx < half) { threefry(k0, k1, idx, idx + half, a, b); return a; }
    else            { threefry(k0, k1, idx - half, idx, a, b); return b; }
#endif
}

// ---------------------------------------------------------------------------
// IoU with XLA-matching fp32 ops (no FMA contraction: *_rn intrinsics).
// ---------------------------------------------------------------------------
__device__ __forceinline__ float f_area(float4 v) {
    return __fmul_rn(__fadd_rn(__fsub_rn(v.z, v.x), 1.0f),
                     __fadd_rn(__fsub_rn(v.w, v.y), 1.0f));
}
__device__ __forceinline__ float f_iou(float4 a, float aa, float4 g, float ag) {
    float wx = __fadd_rn(__fsub_rn(fminf(a.z, g.z), fmaxf(a.x, g.x)), 1.0f);
    wx = fmaxf(wx, 0.0f);
    float wy = __fadd_rn(__fsub_rn(fminf(a.w, g.w), fmaxf(a.y, g.y)), 1.0f);
    wy = fmaxf(wy, 0.0f);
    float inter = __fmul_rn(wx, wy);
    return __fdiv_rn(inter, __fsub_rn(__fadd_rn(aa, ag), inter));
}

// ---------------------------------------------------------------------------
// Scratch (static __device__ — no allocation allowed)
// ---------------------------------------------------------------------------
__device__ uint32_t d_g2a[NB][NG];                 // per-gt col max (float bits)
__device__ uint8_t  d_aidx[NB][N_ANCH];            // argmax gt per anchor
__device__ int8_t   d_lab[NB][N_ANCH];             // labels -1/0/1
__device__ unsigned long long d_poskey[NB][N_ANCH];// packed prio keys of pos
__device__ int      d_negl[NB][N_ANCH];            // compacted neg indices
__device__ int      d_poscnt[NB], d_negcnt[NB], d_tbg[NB], d_dosamp[NB];

// ---------------------------------------------------------------------------
__global__ __launch_bounds__(256) void k_init() {
    int t = threadIdx.x;
    if (t < NB * NG) ((uint32_t*)d_g2a)[t] = 0;
    if (t < NB) { d_poscnt[t] = 0; d_negcnt[t] = 0; }
}

// Pass 1: per-gt column max over all anchors (warp shfl reduce + smem/global
// atomics). grid = (N/(256*4), NB)
__global__ __launch_bounds__(256) void k_colmax(const float4* __restrict__ boxes,
                                                const float4* __restrict__ gt,
                                                const int* __restrict__ gti,
                                                const float* __restrict__ imi) {
    __shared__ uint32_t sg2a[NG];
    __shared__ float4 sgt[NG];
    __shared__ float  sga[NG];
    __shared__ int    sval[NG];
    int b = blockIdx.y, tid = threadIdx.x, lane = tid & 31;
    if (tid < NG) {
        sg2a[tid] = 0;
        float4 g = gt[b * NG + tid];
        sgt[tid] = g; sga[tid] = f_area(g);
        sval[tid] = (gti[b * NG + tid] == 0);
    }
    __syncthreads();
    float limw = __fadd_rn(imi[b * 3 + 1], 1.0f);
    float limh = __fadd_rn(imi[b * 3 + 0], 1.0f);
    int base = blockIdx.x * 256 * 4 + tid;
    for (int it = 0; it < 4; it++) {
        int i = base + it * 256;
        float4 a = boxes[i];
        bool inside = (a.x >= 0.0f) && (a.y >= 0.0f) && (a.z < limw) && (a.w < limh);
        float aa = f_area(a);
        for (int g = 0; g < NG; g++) {
            float v = 0.0f;
            if (inside && sval[g]) v = f_iou(a, aa, sgt[g], sga[g]);
            #pragma unroll
            for (int off = 16; off; off >>= 1)
                v = fmaxf(v, __shfl_xor_sync(FULLMASK, v, off));
            if (lane == 0 && v > 0.0f) atomicMax(&sg2a[g], __float_as_uint(v));
        }
    }
    __syncthreads();
    if (tid < NG && sg2a[tid]) atomicMax(&d_g2a[b][tid], sg2a[tid]);
}

// Pass 2: per-anchor match (a2g max/argmax, with_max, pos/neg classification,
// warp-aggregated list compaction, pos priority keys). grid = (N/256, NB)
__global__ __launch_bounds__(256) void k_match(const float4* __restrict__ boxes,
                                               const float4* __restrict__ gt,
                                               const int* __restrict__ gti,
                                               const float* __restrict__ imi,
                                               Keys keys) {
    __shared__ float4 sgt[NG];
    __shared__ float  sga[NG], sg2af[NG];
    __shared__ int    sval[NG];
    int b = blockIdx.y, tid = threadIdx.x, lane = tid & 31;
    if (tid < NG) {
        float4 g = gt[b * NG + tid];
        sgt[tid] = g; sga[tid] = f_area(g);
        sval[tid] = (gti[b * NG + tid] == 0);
        float f = __uint_as_float(d_g2a[b][tid]);
        sg2af[tid] = (f == 0.0f) ? 1.0f : f;   // where(g2a==0, 1.0, g2a)
    }
    __syncthreads();
    float limw = __fadd_rn(imi[b * 3 + 1], 1.0f);
    float limh = __fadd_rn(imi[b * 3 + 0], 1.0f);
    int i = blockIdx.x * 256 + tid;
    float4 a = boxes[i];
    bool inside = (a.x >= 0.0f) && (a.y >= 0.0f) && (a.z < limw) && (a.w < limh);
    float aa = f_area(a);
    float best = -1.0f; int bidx = 0; bool wm = false;
    for (int g = 0; g < NG; g++) {
        float v = 0.0f;
        if (inside && sval[g]) v = f_iou(a, aa, sgt[g], sga[g]);
        if (v > best) { best = v; bidx = g; }      // first-max tie like argmax
        wm |= (v == sg2af[g]);
    }
    bool pos = inside && (wm || best >= 0.5f);
    bool neg = inside && (best < 0.3f);
    d_aidx[b][i] = (uint8_t)bidx;
    d_lab[b][i] = -1;

    unsigned mneg = __ballot_sync(FULLMASK, neg);
    if (mneg) {
        int leader = __ffs(mneg) - 1, basek = 0;
        if (lane == leader) basek = atomicAdd(&d_negcnt[b], __popc(mneg));
        basek = __shfl_sync(FULLMASK, basek, leader);
        if (neg) d_negl[b][basek + __popc(mneg & ((1u << lane) - 1))] = i;
    }
    unsigned mpos = __ballot_sync(FULLMASK, pos);
    if (mpos) {
        int leader = __ffs(mpos) - 1, basek = 0;
        if (lane == leader) basek = atomicAdd(&d_poscnt[b], __popc(mpos));
        basek = __shfl_sync(FULLMASK, basek, leader);
        if (pos) {
            uint32_t bits = rbits(keys.kp0[b], keys.kp1[b], (uint32_t)i,
                                  (uint32_t)(N_ANCH / 2));
            uint32_t m23 = bits >> 9;  // mantissa: strictly ordered like uniform
            unsigned long long key =
                ((unsigned long long)m23 << 18) | (unsigned)(N_ANCH - 1 - i);
            d_poskey[b][basek + __popc(mpos & ((1u << lane) - 1))] = key;
        }
    }
}

// Pass 3: keep top-TFG positives by priority (rank-by-count, early break).
__global__ __launch_bounds__(256) void k_rank() {
    int b = blockIdx.y;
    int P = d_poscnt[b];
    for (int e = blockIdx.x * 256 + threadIdx.x; e < P; e += gridDim.x * 256) {
        unsigned long long k = d_poskey[b][e];
        int c = 0;
        for (int j = 0; j < P; j++) {
            c += (d_poskey[b][j] > k);
            if (c >= TFG) break;
        }
        if (c < TFG) {
            int i = N_ANCH - 1 - (int)(k & 0x3FFFFu);
            d_lab[b][i] = 1;
        }
    }
}

__global__ void k_counts() {
    int b = threadIdx.x;
    if (b < NB) {
        int nf = min(d_poscnt[b], TFG);
        int tb = SB - nf;
        d_tbg[b] = tb;
        d_dosamp[b] = (d_negcnt[b] > tb) ? 1 : 0;
    }
}

// Pass 4: categorical sampling. One block per (sample s, image b); argmax of
// 23-bit uniform mantissa over the compacted neg list (gumbel is monotone in
// it). Packed u64 key reproduces argmax first-index tie-breaking.
__global__ __launch_bounds__(256) void k_sample(Keys keys) {
    __shared__ unsigned long long sred[256];
    int b = blockIdx.y, s = blockIdx.x, tid = threadIdx.x;
    if (!d_dosamp[b] || s >= d_tbg[b]) return;
    int M = d_negcnt[b];
    uint32_t k0 = keys.kn0[b], k1 = keys.kn1[b];
    uint32_t base = (uint32_t)s * (uint32_t)N_ANCH;
    unsigned long long best = 0;
    for (int t = tid; t < M; t += 1024) {
        #pragma unroll
        for (int u = 0; u < 4; u++) {       // 4 independent chains for ILP
            int tt = t + u * 256;
            if (tt < M) {
                int i = d_negl[b][tt];
                uint32_t bits = rbits(k0, k1, base + (uint32_t)i,
                                      (uint32_t)(SB / 2) * (uint32_t)N_ANCH);
                unsigned long long key =
                    ((unsigned long long)((bits >> 9) + 1u) << 18) |
                    (unsigned)(N_ANCH - 1 - i);
                best = max(best, key);
            }
        }
    }
    sred[tid] = best;
    __syncthreads();
    for (int off = 128; off; off >>= 1) {
        if (tid < off) sred[tid] = max(sred[tid], sred[tid + off]);
        __syncthreads();
    }
    if (tid == 0) {
        int i = N_ANCH - 1 - (int)(sred[0] & 0x3FFFFu);
        d_lab[b][i] = 0;                    // scatter .set(0)
    }
}

// Pass 5: emit labels (as float) + bbox regression targets.
__global__ __launch_bounds__(256) void k_out(const float4* __restrict__ boxes,
                                             const float4* __restrict__ gt,
                                             float* __restrict__ outL,
                                             float4* __restrict__ outB) {
    __shared__ float4 sgt[NG];
    int b = blockIdx.y, tid = threadIdx.x;
    if (tid < NG) sgt[tid] = gt[b * NG + tid];
    __syncthreads();
    int i = blockIdx.x * 256 + tid;
    int lab = d_lab[b][i];
    outL[b * N_ANCH + i] = (float)lab;
    float4 t = make_float4(0.f, 0.f, 0.f, 0.f);
    if (lab > 0) {
        float4 a = boxes[i];
        float4 g = sgt[d_aidx[b][i]];
        float ew = a.z - a.x + 1.0f, eh = a.w - a.y + 1.0f;
        float ecx = a.x + 0.5f * ew, ecy = a.y + 0.5f * eh;
        float gw = g.z - g.x + 1.0f, gh = g.w - g.y + 1.0f;
        float gcx = g.x + 0.5f * gw, gcy = g.y + 0.5f * gh;
        t.x = (gcx - ecx) / ew;
        t.y = (gcy - ecy) / eh;
        t.z = logf(gw / ew);
        t.w = logf(gh / eh);
    }
    outB[b * N_ANCH + i] = t;
}

// ---------------------------------------------------------------------------
extern "C" void kernel_launch(void* const* d_in, const int* in_sizes, int n_in,
                              void* d_out, int out_size) {
    const float4* boxes = (const float4*)d_in[0];
    const float4* gt    = (const float4*)d_in[1];
    const int*    gti   = (const int*)d_in[3];   // gt_ignore_labels
    const float*  imi   = (const float*)d_in[4]; // im_info
    float* out = (float*)d_out;

    // Host-side key derivation (deterministic; matches jax.random.key(42)).
    Keys keys;
#if JAX_PARTITIONABLE
    for (int b = 0; b < NB; b++) {
        uint32_t kb0, kb1;
        threefry(0u, 42u, 0u, (uint32_t)b, kb0, kb1);        // fold-like split
        threefry(kb0, kb1, 0u, 0u, keys.kp0[b], keys.kp1[b]); // kp
        threefry(kb0, kb1, 0u, 1u, keys.kn0[b], keys.kn1[b]); // kn
    }
#else
    uint32_t o0[4], o1[4];
    for (int j = 0; j < 4; j++) threefry(0u, 42u, (uint32_t)j, (uint32_t)(j + 4), o0[j], o1[j]);
    uint32_t kb[NB][2] = {{o0[0], o0[1]}, {o0[2], o0[3]}, {o1[0], o1[1]}, {o1[2], o1[3]}};
    for (int b = 0; b < NB; b++) {
        uint32_t p0[2], p1[2];
        threefry(kb[b][0], kb[b][1], 0u, 2u, p0[0], p1[0]);
        threefry(kb[b][0], kb[b][1], 1u, 3u, p0[1], p1[1]);
        keys.kp0[b] = p0[0]; keys.kp1[b] = p0[1];
        keys.kn0[b] = p1[0]; keys.kn1[b] = p1[1];
    }
#endif

    k_init<<<1, 256>>>();
    k_colmax<<<dim3(N_ANCH / 1024, NB), 256>>>(boxes, gt, gti, imi);
    k_match<<<dim3(N_ANCH / 256, NB), 256>>>(boxes, gt, gti, imi, keys);
    k_rank<<<dim3(64, NB), 256>>>();
    k_counts<<<1, 32>>>();
    k_sample<<<dim3(SB, NB), 256>>>(keys);
    k_out<<<dim3(N_ANCH / 256, NB), 256>>>(boxes, gt, out,
                                           (float4*)(out + NB * N_ANCH));
}

// round 3
// speedup vs baseline: 1.0114x; 1.0114x over previous
#include <cuda_runtime.h>
#include <cstdint>

// ============================================================================
// RPN GT matcher — bit-exact JAX Threefry (partitionable) + integer-monotone
// shortcuts for gumbel/uniform ordering.
// R2: O(P) histogram-select replaces O(P^2) rank; sampler batches 8 samples
// per block to amortize index loads / loop overhead.
// ============================================================================

#define N_ANCH 262144
#define NB 4
#define NG 64
#define TFG 153          // TARGET_FG
#define SB 512           // SAMPLE_BATCH
#define SBATCH 8         // samples per block in k_sample
#define FULLMASK 0xFFFFFFFFu

struct Keys { uint32_t kp0[NB], kp1[NB], kn0[NB], kn1[NB]; };

__host__ __device__ __forceinline__ uint32_t rotl32(uint32_t x, int r) {
#ifdef __CUDA_ARCH__
    return __funnelshift_l(x, x, r);
#else
    return (x << r) | (x >> (32 - r));
#endif
}

// Threefry-2x32, 20 rounds, exactly as jax._src.prng.threefry2x32
__host__ __device__ __forceinline__ void threefry(uint32_t k0, uint32_t k1,
                                                  uint32_t x0, uint32_t x1,
                                                  uint32_t& o0, uint32_t& o1) {
    uint32_t ks2 = k0 ^ k1 ^ 0x1BD11BDAu;
    x0 += k0; x1 += k1;
#define TFR(r) { x0 += x1; x1 = rotl32(x1, r); x1 ^= x0; }
    TFR(13) TFR(15) TFR(26) TFR(6)
    x0 += k1;  x1 += ks2 + 1u;
    TFR(17) TFR(29) TFR(16) TFR(24)
    x0 += ks2; x1 += k0 + 2u;
    TFR(13) TFR(15) TFR(26) TFR(6)
    x0 += k0;  x1 += k1 + 3u;
    TFR(17) TFR(29) TFR(16) TFR(24)
    x0 += k1;  x1 += ks2 + 4u;
    TFR(13) TFR(15) TFR(26) TFR(6)
    x0 += ks2; x1 += k0 + 5u;
#undef TFR
    o0 = x0; o1 = x1;
}

// Partitionable random 32-bit word at flat index idx: counter (0, idx), o0^o1
__device__ __forceinline__ uint32_t rbits(uint32_t k0, uint32_t k1, uint32_t idx) {
    uint32_t a, b; threefry(k0, k1, 0u, idx, a, b);
    return a ^ b;
}

// ---------------------------------------------------------------------------
// IoU with XLA-matching fp32 ops (no FMA contraction: *_rn intrinsics).
// ---------------------------------------------------------------------------
__device__ __forceinline__ float f_area(float4 v) {
    return __fmul_rn(__fadd_rn(__fsub_rn(v.z, v.x), 1.0f),
                     __fadd_rn(__fsub_rn(v.w, v.y), 1.0f));
}
__device__ __forceinline__ float f_iou(float4 a, float aa, float4 g, float ag) {
    float wx = __fadd_rn(__fsub_rn(fminf(a.z, g.z), fmaxf(a.x, g.x)), 1.0f);
    wx = fmaxf(wx, 0.0f);
    float wy = __fadd_rn(__fsub_rn(fminf(a.w, g.w), fmaxf(a.y, g.y)), 1.0f);
    wy = fmaxf(wy, 0.0f);
    float inter = __fmul_rn(wx, wy);
    return __fdiv_rn(inter, __fsub_rn(__fadd_rn(aa, ag), inter));
}

// ---------------------------------------------------------------------------
// Scratch (static __device__ — no allocation allowed)
// ---------------------------------------------------------------------------
__device__ uint32_t d_g2a[NB][NG];                 // per-gt col max (float bits)
__device__ uint8_t  d_aidx[NB][N_ANCH];            // argmax gt per anchor
__device__ int8_t   d_lab[NB][N_ANCH];             // labels -1/0/1
__device__ unsigned long long d_poskey[NB][N_ANCH];// packed prio keys of pos
__device__ int      d_negl[NB][N_ANCH];            // compacted neg indices
__device__ int      d_poscnt[NB], d_negcnt[NB], d_tbg[NB], d_dosamp[NB];

// ---------------------------------------------------------------------------
__global__ __launch_bounds__(256) void k_init() {
    int t = threadIdx.x;
    if (t < NB * NG) ((uint32_t*)d_g2a)[t] = 0;
    if (t < NB) { d_poscnt[t] = 0; d_negcnt[t] = 0; }
}

// Pass 1: per-gt column max over all anchors.
__global__ __launch_bounds__(256) void k_colmax(const float4* __restrict__ boxes,
                                                const float4* __restrict__ gt,
                                                const int* __restrict__ gti,
                                                const float* __restrict__ imi) {
    __shared__ uint32_t sg2a[NG];
    __shared__ float4 sgt[NG];
    __shared__ float  sga[NG];
    __shared__ int    sval[NG];
    int b = blockIdx.y, tid = threadIdx.x, lane = tid & 31;
    if (tid < NG) {
        sg2a[tid] = 0;
        float4 g = gt[b * NG + tid];
        sgt[tid] = g; sga[tid] = f_area(g);
        sval[tid] = (gti[b * NG + tid] == 0);
    }
    __syncthreads();
    float limw = __fadd_rn(imi[b * 3 + 1], 1.0f);
    float limh = __fadd_rn(imi[b * 3 + 0], 1.0f);
    int base = blockIdx.x * 256 * 4 + tid;
    for (int it = 0; it < 4; it++) {
        int i = base + it * 256;
        float4 a = boxes[i];
        bool inside = (a.x >= 0.0f) && (a.y >= 0.0f) && (a.z < limw) && (a.w < limh);
        float aa = f_area(a);
        for (int g = 0; g < NG; g++) {
            float v = 0.0f;
            if (inside && sval[g]) v = f_iou(a, aa, sgt[g], sga[g]);
            #pragma unroll
            for (int off = 16; off; off >>= 1)
                v = fmaxf(v, __shfl_xor_sync(FULLMASK, v, off));
            if (lane == 0 && v > 0.0f) atomicMax(&sg2a[g], __float_as_uint(v));
        }
    }
    __syncthreads();
    if (tid < NG && sg2a[tid]) atomicMax(&d_g2a[b][tid], sg2a[tid]);
}

// Pass 2: per-anchor match + classification + compaction + priority keys.
__global__ __launch_bounds__(256) void k_match(const float4* __restrict__ boxes,
                                               const float4* __restrict__ gt,
                                               const int* __restrict__ gti,
                                               const float* __restrict__ imi,
                                               Keys keys) {
    __shared__ float4 sgt[NG];
    __shared__ float  sga[NG], sg2af[NG];
    __shared__ int    sval[NG];
    int b = blockIdx.y, tid = threadIdx.x, lane = tid & 31;
    if (tid < NG) {
        float4 g = gt[b * NG + tid];
        sgt[tid] = g; sga[tid] = f_area(g);
        sval[tid] = (gti[b * NG + tid] == 0);
        float f = __uint_as_float(d_g2a[b][tid]);
        sg2af[tid] = (f == 0.0f) ? 1.0f : f;   // where(g2a==0, 1.0, g2a)
    }
    __syncthreads();
    float limw = __fadd_rn(imi[b * 3 + 1], 1.0f);
    float limh = __fadd_rn(imi[b * 3 + 0], 1.0f);
    int i = blockIdx.x * 256 + tid;
    float4 a = boxes[i];
    bool inside = (a.x >= 0.0f) && (a.y >= 0.0f) && (a.z < limw) && (a.w < limh);
    float aa = f_area(a);
    float best = -1.0f; int bidx = 0; bool wm = false;
    for (int g = 0; g < NG; g++) {
        float v = 0.0f;
        if (inside && sval[g]) v = f_iou(a, aa, sgt[g], sga[g]);
        if (v > best) { best = v; bidx = g; }      // first-max tie like argmax
        wm |= (v == sg2af[g]);
    }
    bool pos = inside && (wm || best >= 0.5f);
    bool neg = inside && (best < 0.3f);
    d_aidx[b][i] = (uint8_t)bidx;
    d_lab[b][i] = -1;

    unsigned mneg = __ballot_sync(FULLMASK, neg);
    if (mneg) {
        int leader = __ffs(mneg) - 1, basek = 0;
        if (lane == leader) basek = atomicAdd(&d_negcnt[b], __popc(mneg));
        basek = __shfl_sync(FULLMASK, basek, leader);
        if (neg) d_negl[b][basek + __popc(mneg & ((1u << lane) - 1))] = i;
    }
    unsigned mpos = __ballot_sync(FULLMASK, pos);
    if (mpos) {
        int leader = __ffs(mpos) - 1, basek = 0;
        if (lane == leader) basek = atomicAdd(&d_poscnt[b], __popc(mpos));
        basek = __shfl_sync(FULLMASK, basek, leader);
        if (pos) {
            uint32_t bits = rbits(keys.kp0[b], keys.kp1[b], (uint32_t)i);
            uint32_t m23 = bits >> 9;  // mantissa: strictly ordered like uniform
            unsigned long long key =
                ((unsigned long long)m23 << 18) | (unsigned)(N_ANCH - 1 - i);
            d_poskey[b][basek + __popc(mpos & ((1u << lane) - 1))] = key;
        }
    }
}

// Pass 3: O(P) top-TFG selection via 4096-bin histogram on top-12 mantissa
// bits + exact rank inside the threshold bin. One block per image.
// Also computes tbg/dosamp (replaces k_counts).
#define NBIN 4096
#define BINCAP 2048
__global__ __launch_bounds__(1024) void k_select() {
    __shared__ uint32_t hist[NBIN];
    __shared__ unsigned long long binkeys[BINCAP];
    __shared__ int s_thr, s_need, s_cnt;
    int b = blockIdx.x, tid = threadIdx.x;
    int P = d_poscnt[b];
    if (tid == 0) {
        int nf = min(P, TFG);
        int tb = SB - nf;
        d_tbg[b] = tb;
        d_dosamp[b] = (d_negcnt[b] > tb) ? 1 : 0;
    }
    if (P <= TFG) {
        // all positives stay label 1
        for (int e = tid; e < P; e += 1024) {
            unsigned long long k = d_poskey[b][e];
            d_lab[b][N_ANCH - 1 - (int)(k & 0x3FFFFu)] = 1;
        }
        return;
    }
    for (int i = tid; i < NBIN; i += 1024) hist[i] = 0;
    __syncthreads();
    for (int e = tid; e < P; e += 1024)
        atomicAdd(&hist[(int)(d_poskey[b][e] >> 29)], 1u);
    __syncthreads();
    if (tid == 0) {
        int cum = 0, t = 0, need = TFG;
        for (int bin = NBIN - 1; bin >= 0; bin--) {
            int c = (int)hist[bin];
            if (cum + c >= TFG) { t = bin; need = TFG - cum; break; }
            cum += c;
        }
        s_thr = t; s_need = need; s_cnt = 0;
    }
    __syncthreads();
    int t = s_thr, need = s_need;
    for (int e = tid; e < P; e += 1024) {
        unsigned long long k = d_poskey[b][e];
        int bin = (int)(k >> 29);
        if (bin > t) {
            d_lab[b][N_ANCH - 1 - (int)(k & 0x3FFFFu)] = 1;
        } else if (bin == t) {
            int p = atomicAdd(&s_cnt, 1);
            if (p < BINCAP) binkeys[p] = k;
        }
    }
    __syncthreads();
    int C = min(s_cnt, BINCAP);
    for (int e = tid; e < C; e += 1024) {
        unsigned long long k = binkeys[e];
        int c = 0;
        for (int j = 0; j < C; j++) c += (binkeys[j] > k);
        if (c < need) d_lab[b][N_ANCH - 1 - (int)(k & 0x3FFFFu)] = 1;
    }
}

// Pass 4: categorical sampling. One block per (8 samples, image). Argmax of
// packed (mantissa+1, N-1-i) over the compacted neg list — gumbel is strictly
// monotone in the 23-bit mantissa, ties resolve to first index.
__global__ __launch_bounds__(256) void k_sample(Keys keys) {
    __shared__ unsigned long long red[SBATCH][8];
    int b = blockIdx.y, tid = threadIdx.x;
    int s0 = blockIdx.x * SBATCH;
    int tbg = d_tbg[b];
    if (!d_dosamp[b] || s0 >= tbg) return;
    int M = d_negcnt[b];
    uint32_t k0 = keys.kn0[b], k1 = keys.kn1[b];

    unsigned long long best[SBATCH];
    #pragma unroll
    for (int u = 0; u < SBATCH; u++) best[u] = 0ull;

    for (int t = tid; t < M; t += 256) {
        uint32_t i = (uint32_t)__ldg(&d_negl[b][t]);
        unsigned long long lowtag = (unsigned)(N_ANCH - 1 - (int)i);
        uint32_t ctr0 = (uint32_t)s0 * (uint32_t)N_ANCH + i;
        #pragma unroll
        for (int u = 0; u < SBATCH; u++) {
            uint32_t bits = rbits(k0, k1, ctr0 + (uint32_t)u * (uint32_t)N_ANCH);
            unsigned long long key =
                ((unsigned long long)((bits >> 9) + 1u) << 18) | lowtag;
            best[u] = max(best[u], key);
        }
    }
    // warp reduce each of the SBATCH maxes, then cross-warp via smem
    int lane = tid & 31, wid = tid >> 5;
    #pragma unroll
    for (int u = 0; u < SBATCH; u++) {
        unsigned long long v = best[u];
        #pragma unroll
        for (int off = 16; off; off >>= 1) {
            unsigned long long o = __shfl_xor_sync(FULLMASK, v, off);
            v = max(v, o);
        }
        if (lane == 0) red[u][wid] = v;
    }
    __syncthreads();
    if (tid < SBATCH) {
        unsigned long long v = red[tid][0];
        #pragma unroll
        for (int w = 1; w < 8; w++) v = max(v, red[tid][w]);
        if (s0 + tid < tbg) {
            int i = N_ANCH - 1 - (int)(v & 0x3FFFFu);
            d_lab[b][i] = 0;
        }
    }
}

// Pass 5: emit labels (as float) + bbox regression targets.
__global__ __launch_bounds__(256) void k_out(const float4* __restrict__ boxes,
                                             const float4* __restrict__ gt,
                                             float* __restrict__ outL,
                                             float4* __restrict__ outB) {
    __shared__ float4 sgt[NG];
    int b = blockIdx.y, tid = threadIdx.x;
    if (tid < NG) sgt[tid] = gt[b * NG + tid];
    __syncthreads();
    int i = blockIdx.x * 256 + tid;
    int lab = d_lab[b][i];
    outL[b * N_ANCH + i] = (float)lab;
    float4 t = make_float4(0.f, 0.f, 0.f, 0.f);
    if (lab > 0) {
        float4 a = boxes[i];
        float4 g = sgt[d_aidx[b][i]];
        float ew = a.z - a.x + 1.0f, eh = a.w - a.y + 1.0f;
        float ecx = a.x + 0.5f * ew, ecy = a.y + 0.5f * eh;
        float gw = g.z - g.x + 1.0f, gh = g.w - g.y + 1.0f;
        float gcx = g.x + 0.5f * gw, gcy = g.y + 0.5f * gh;
        t.x = (gcx - ecx) / ew;
        t.y = (gcy - ecy) / eh;
        t.z = logf(gw / ew);
        t.w = logf(gh / eh);
    }
    outB[b * N_ANCH + i] = t;
}

// ---------------------------------------------------------------------------
extern "C" void kernel_launch(void* const* d_in, const int* in_sizes, int n_in,
                              void* d_out, int out_size) {
    const float4* boxes = (const float4*)d_in[0];
    const float4* gt    = (const float4*)d_in[1];
    const int*    gti   = (const int*)d_in[3];   // gt_ignore_labels
    const float*  imi   = (const float*)d_in[4]; // im_info
    float* out = (float*)d_out;

    // Host-side key derivation (jax.random.key(42), partitionable threefry).
    Keys keys;
    for (int b = 0; b < NB; b++) {
        uint32_t kb0, kb1;
        threefry(0u, 42u, 0u, (uint32_t)b, kb0, kb1);         // split(key,B)[b]
        threefry(kb0, kb1, 0u, 0u, keys.kp0[b], keys.kp1[b]); // kp
        threefry(kb0, kb1, 0u, 1u, keys.kn0[b], keys.kn1[b]); // kn
    }

    k_init<<<1, 256>>>();
    k_colmax<<<dim3(N_ANCH / 1024, NB), 256>>>(boxes, gt, gti, imi);
    k_match<<<dim3(N_ANCH / 256, NB), 256>>>(boxes, gt, gti, imi, keys);
    k_select<<<NB, 1024>>>();
    k_sample<<<dim3(SB / SBATCH, NB), 256>>>(keys);
    k_out<<<dim3(N_ANCH / 256, NB), 256>>>(boxes, gt, out,
                                           (float4*)(out + NB * N_ANCH));
}

// round 4
// speedup vs baseline: 1.6057x; 1.5876x over previous
#include <cuda_runtime.h>
#include <cstdint>

// ============================================================================
// RPN GT matcher — bit-exact JAX Threefry (partitionable), integer-monotone
// gumbel/uniform ordering, GT spatial binning, slim u32 sampler.
// ============================================================================

#define N_ANCH 262144
#define NB 4
#define NG 64
#define TFG 153          // TARGET_FG
#define SB 512           // SAMPLE_BATCH
#define SBT 2            // samples per block in k_sample
#define FULLMASK 0xFFFFFFFFu
#define NCELL 256        // 16x16 cells of 64px

struct Keys { uint32_t kp0[NB], kp1[NB], kn0[NB], kn1[NB]; };

__host__ __device__ __forceinline__ uint32_t rotl32(uint32_t x, int r) {
#ifdef __CUDA_ARCH__
    return __funnelshift_l(x, x, r);
#else
    return (x << r) | (x >> (32 - r));
#endif
}

// Threefry-2x32, 20 rounds, exactly as jax._src.prng.threefry2x32
__host__ __device__ __forceinline__ void threefry(uint32_t k0, uint32_t k1,
                                                  uint32_t x0, uint32_t x1,
                                                  uint32_t& o0, uint32_t& o1) {
    uint32_t ks2 = k0 ^ k1 ^ 0x1BD11BDAu;
    x0 += k0; x1 += k1;
#define TFR(r) { x0 += x1; x1 = rotl32(x1, r); x1 ^= x0; }
    TFR(13) TFR(15) TFR(26) TFR(6)
    x0 += k1;  x1 += ks2 + 1u;
    TFR(17) TFR(29) TFR(16) TFR(24)
    x0 += ks2; x1 += k0 + 2u;
    TFR(13) TFR(15) TFR(26) TFR(6)
    x0 += k0;  x1 += k1 + 3u;
    TFR(17) TFR(29) TFR(16) TFR(24)
    x0 += k1;  x1 += ks2 + 4u;
    TFR(13) TFR(15) TFR(26) TFR(6)
    x0 += ks2; x1 += k0 + 5u;
#undef TFR
    o0 = x0; o1 = x1;
}

// Partitionable random 32-bit word at flat index idx: counter (0, idx), o0^o1
__device__ __forceinline__ uint32_t rbits(uint32_t k0, uint32_t k1, uint32_t idx) {
    uint32_t a, b; threefry(k0, k1, 0u, idx, a, b);
    return a ^ b;
}

// ---------------------------------------------------------------------------
__device__ __forceinline__ float f_area(float4 v) {
    return __fmul_rn(__fadd_rn(__fsub_rn(v.z, v.x), 1.0f),
                     __fadd_rn(__fsub_rn(v.w, v.y), 1.0f));
}

// ---------------------------------------------------------------------------
// Scratch (static __device__ — no allocation allowed)
// ---------------------------------------------------------------------------
__device__ uint32_t d_g2a[NB][NG];
__device__ uint8_t  d_aidx[NB][N_ANCH];
__device__ int8_t   d_lab[NB][N_ANCH];
__device__ unsigned long long d_poskey[NB][N_ANCH];
__device__ int      d_negl[NB][N_ANCH];
__device__ int      d_poscnt[NB], d_negcnt[NB], d_tbg[NB], d_dosamp[NB];
__device__ __align__(16) uint8_t d_cellgt[NB][NCELL][64];
__device__ int      d_cellcnt[NB][NCELL];

// ---------------------------------------------------------------------------
__global__ __launch_bounds__(256) void k_init() {
    int t = threadIdx.x;
    if (t < NB * NG) ((uint32_t*)d_g2a)[t] = 0;
    if (t < NB) { d_poscnt[t] = 0; d_negcnt[t] = 0; }
}

// Bin valid GTs into 16x16 cells keyed by anchor (x1,y1) position. A GT is
// relevant to a cell iff some anchor with x1 in the cell (w<160.5, +1 box
// convention) can intersect it. Margins are generous.
__global__ __launch_bounds__(256) void k_bins(const float4* __restrict__ gt,
                                              const int* __restrict__ gti) {
    int t = blockIdx.x * 256 + threadIdx.x;
    int b = t >> 8, c = t & 255;
    int cx = c & 15, cy = c >> 4;
    float x0 = cx * 64.0f, y0 = cy * 64.0f;
    int n = 0;
    for (int g = 0; g < NG; g++) {
        if (gti[b * NG + g] != 0) continue;
        float4 gb = gt[b * NG + g];
        bool ox = (gb.z >= x0 - 1.5f) && (gb.x <= x0 + 226.5f);
        bool oy = (gb.w >= y0 - 1.5f) && (gb.y <= y0 + 226.5f);
        if (ox && oy) d_cellgt[b][c][n++] = (uint8_t)g;
    }
    d_cellcnt[b][c] = n;
}

// Pass 1: per-gt column max. Binned candidates; divide only when inter>0
// (exact: iou==0 bits otherwise); direct smem atomicMax (no shfl).
__global__ __launch_bounds__(256) void k_colmax(const float4* __restrict__ boxes,
                                                const float4* __restrict__ gt,
                                                const float* __restrict__ imi) {
    __shared__ float4 sgt[NG];
    __shared__ float  sga[NG];
    __shared__ uint32_t sg2a[NG];
    __shared__ uint8_t slist[NCELL * 64];
    __shared__ int     scnt[NCELL];
    int b = blockIdx.y, tid = threadIdx.x;
    if (tid < NG) {
        sg2a[tid] = 0;
        float4 g = gt[b * NG + tid];
        sgt[tid] = g; sga[tid] = f_area(g);
    }
    { // 16KB list + counts
        const int4* src = (const int4*)d_cellgt[b];
        int4* dst = (int4*)slist;
        for (int k = tid; k < NCELL * 64 / 16; k += 256) dst[k] = src[k];
        scnt[tid] = d_cellcnt[b][tid];
    }
    __syncthreads();
    float limw = __fadd_rn(imi[b * 3 + 1], 1.0f);
    float limh = __fadd_rn(imi[b * 3 + 0], 1.0f);
    int base = blockIdx.x * 1024 + tid;
    for (int it = 0; it < 4; it++) {
        int i = base + it * 256;
        float4 a = boxes[i];
        bool inside = (a.x >= 0.0f) && (a.y >= 0.0f) && (a.z < limw) && (a.w < limh);
        if (!inside) continue;
        float aa = f_area(a);
        int cx = min((int)(a.x * (1.0f / 64.0f)), 15);
        int cy = min((int)(a.y * (1.0f / 64.0f)), 15);
        int c = cy * 16 + cx;
        int n = scnt[c];
        const uint8_t* lp = &slist[c * 64];
        for (int j = 0; j < n; j++) {
            int g = lp[j];
            float4 gb = sgt[g];
            float wx = __fadd_rn(__fsub_rn(fminf(a.z, gb.z), fmaxf(a.x, gb.x)), 1.0f);
            float wy = __fadd_rn(__fsub_rn(fminf(a.w, gb.w), fmaxf(a.y, gb.y)), 1.0f);
            wx = fmaxf(wx, 0.0f); wy = fmaxf(wy, 0.0f);
            float inter = __fmul_rn(wx, wy);
            if (inter > 0.0f) {
                float v = __fdiv_rn(inter, __fsub_rn(__fadd_rn(aa, sga[g]), inter));
                atomicMax(&sg2a[g], __float_as_uint(v));
            }
        }
    }
    __syncthreads();
    if (tid < NG && sg2a[tid]) atomicMax(&d_g2a[b][tid], sg2a[tid]);
}

// Pass 2: per-anchor match + classification + compaction + priority keys.
__global__ __launch_bounds__(256) void k_match(const float4* __restrict__ boxes,
                                               const float4* __restrict__ gt,
                                               const float* __restrict__ imi,
                                               Keys keys) {
    __shared__ float4 sgt[NG];
    __shared__ float  sga[NG], sg2af[NG];
    __shared__ uint8_t slist[NCELL * 64];
    __shared__ int     scnt[NCELL];
    int b = blockIdx.y, tid = threadIdx.x, lane = tid & 31;
    if (tid < NG) {
        float4 g = gt[b * NG + tid];
        sgt[tid] = g; sga[tid] = f_area(g);
        float f = __uint_as_float(d_g2a[b][tid]);
        sg2af[tid] = (f == 0.0f) ? 1.0f : f;   // where(g2a==0, 1.0, g2a)
    }
    {
        const int4* src = (const int4*)d_cellgt[b];
        int4* dst = (int4*)slist;
        for (int k = tid; k < NCELL * 64 / 16; k += 256) dst[k] = src[k];
        scnt[tid] = d_cellcnt[b][tid];
    }
    __syncthreads();
    float limw = __fadd_rn(imi[b * 3 + 1], 1.0f);
    float limh = __fadd_rn(imi[b * 3 + 0], 1.0f);
    int base = blockIdx.x * 1024 + tid;
    for (int it = 0; it < 4; it++) {
        int i = base + it * 256;
        float4 a = boxes[i];
        bool inside = (a.x >= 0.0f) && (a.y >= 0.0f) && (a.z < limw) && (a.w < limh);
        float best = 0.0f; int bidx = 0; bool wm = false;
        if (inside) {
            float aa = f_area(a);
            int cx = min((int)(a.x * (1.0f / 64.0f)), 15);
            int cy = min((int)(a.y * (1.0f / 64.0f)), 15);
            int c = cy * 16 + cx;
            int n = scnt[c];
            const uint8_t* lp = &slist[c * 64];
            for (int j = 0; j < n; j++) {
                int g = lp[j];
                float4 gb = sgt[g];
                float wx = __fadd_rn(__fsub_rn(fminf(a.z, gb.z), fmaxf(a.x, gb.x)), 1.0f);
                float wy = __fadd_rn(__fsub_rn(fminf(a.w, gb.w), fmaxf(a.y, gb.y)), 1.0f);
                wx = fmaxf(wx, 0.0f); wy = fmaxf(wy, 0.0f);
                float inter = __fmul_rn(wx, wy);
                if (inter > 0.0f) {
                    float v = __fdiv_rn(inter, __fsub_rn(__fadd_rn(aa, sga[g]), inter));
                    if (v > best) { best = v; bidx = g; }  // zeros -> idx 0 default
                    wm |= (v == sg2af[g]);
                }
            }
        }
        bool pos = inside && (wm || best >= 0.5f);
        bool neg = inside && (best < 0.3f);
        d_aidx[b][i] = (uint8_t)bidx;
        d_lab[b][i] = -1;

        unsigned mneg = __ballot_sync(FULLMASK, neg);
        if (mneg) {
            int leader = __ffs(mneg) - 1, basek = 0;
            if (lane == leader) basek = atomicAdd(&d_negcnt[b], __popc(mneg));
            basek = __shfl_sync(FULLMASK, basek, leader);
            if (neg) d_negl[b][basek + __popc(mneg & ((1u << lane) - 1))] = i;
        }
        unsigned mpos = __ballot_sync(FULLMASK, pos);
        if (mpos) {
            int leader = __ffs(mpos) - 1, basek = 0;
            if (lane == leader) basek = atomicAdd(&d_poscnt[b], __popc(mpos));
            basek = __shfl_sync(FULLMASK, basek, leader);
            if (pos) {
                uint32_t bits = rbits(keys.kp0[b], keys.kp1[b], (uint32_t)i);
                uint32_t m23 = bits >> 9;
                unsigned long long key =
                    ((unsigned long long)m23 << 18) | (unsigned)(N_ANCH - 1 - i);
                d_poskey[b][basek + __popc(mpos & ((1u << lane) - 1))] = key;
            }
        }
    }
}

// Pass 3: O(P) top-TFG selection via histogram + exact rank in threshold bin.
#define NBIN 4096
#define BINCAP 2048
__global__ __launch_bounds__(1024) void k_select() {
    __shared__ uint32_t hist[NBIN];
    __shared__ unsigned long long binkeys[BINCAP];
    __shared__ int s_thr, s_need, s_cnt;
    int b = blockIdx.x, tid = threadIdx.x;
    int P = d_poscnt[b];
    if (tid == 0) {
        int nf = min(P, TFG);
        int tb = SB - nf;
        d_tbg[b] = tb;
        d_dosamp[b] = (d_negcnt[b] > tb) ? 1 : 0;
    }
    if (P <= TFG) {
        for (int e = tid; e < P; e += 1024) {
            unsigned long long k = d_poskey[b][e];
            d_lab[b][N_ANCH - 1 - (int)(k & 0x3FFFFu)] = 1;
        }
        return;
    }
    for (int i = tid; i < NBIN; i += 1024) hist[i] = 0;
    __syncthreads();
    for (int e = tid; e < P; e += 1024)
        atomicAdd(&hist[(int)(d_poskey[b][e] >> 29)], 1u);
    __syncthreads();
    if (tid == 0) {
        int cum = 0, t = 0, need = TFG;
        for (int bin = NBIN - 1; bin >= 0; bin--) {
            int c = (int)hist[bin];
            if (cum + c >= TFG) { t = bin; need = TFG - cum; break; }
            cum += c;
        }
        s_thr = t; s_need = need; s_cnt = 0;
    }
    __syncthreads();
    int t = s_thr, need = s_need;
    for (int e = tid; e < P; e += 1024) {
        unsigned long long k = d_poskey[b][e];
        int bin = (int)(k >> 29);
        if (bin > t) {
            d_lab[b][N_ANCH - 1 - (int)(k & 0x3FFFFu)] = 1;
        } else if (bin == t) {
            int p = atomicAdd(&s_cnt, 1);
            if (p < BINCAP) binkeys[p] = k;
        }
    }
    __syncthreads();
    int C = min(s_cnt, BINCAP);
    for (int e = tid; e < C; e += 1024) {
        unsigned long long k = binkeys[e];
        int c = 0;
        for (int j = 0; j < C; j++) c += (binkeys[j] > k);
        if (c < need) d_lab[b][N_ANCH - 1 - (int)(k & 0x3FFFFu)] = 1;
    }
}

// Pass 4: categorical sampling. SBT samples per block; u32 masked-mantissa
// running max with rare tie-break branch; exact smallest-index tie-break
// carried through warp/block reductions.
__global__ __launch_bounds__(256) void k_sample(Keys keys) {
    __shared__ uint32_t redv[SBT][8];
    __shared__ uint32_t redi[SBT][8];
    int b = blockIdx.y, tid = threadIdx.x;
    int s0 = blockIdx.x * SBT;
    int tbg = d_tbg[b];
    if (!d_dosamp[b] || s0 >= tbg) return;
    int M = d_negcnt[b];
    uint32_t k0 = keys.kn0[b], k1 = keys.kn1[b];

    uint32_t bv0 = 0, bi0 = 0xFFFFFFFFu, bv1 = 0, bi1 = 0xFFFFFFFFu;
    const int* negl = d_negl[b];
    for (int t = tid; t < M; t += 256) {
        uint32_t i = (uint32_t)__ldg(&negl[t]);
        uint32_t c0 = (uint32_t)s0 * (uint32_t)N_ANCH + i;
        uint32_t r0 = rbits(k0, k1, c0) & 0xFFFFFE00u;
        if (r0 >= bv0) { if (r0 > bv0 || i < bi0) { bv0 = r0; bi0 = i; } }
        uint32_t r1 = rbits(k0, k1, c0 + (uint32_t)N_ANCH) & 0xFFFFFE00u;
        if (r1 >= bv1) { if (r1 > bv1 || i < bi1) { bv1 = r1; bi1 = i; } }
    }
    int lane = tid & 31, wid = tid >> 5;
    #pragma unroll
    for (int off = 16; off; off >>= 1) {
        uint32_t ov = __shfl_xor_sync(FULLMASK, bv0, off);
        uint32_t oi = __shfl_xor_sync(FULLMASK, bi0, off);
        if (ov > bv0 || (ov == bv0 && oi < bi0)) { bv0 = ov; bi0 = oi; }
        ov = __shfl_xor_sync(FULLMASK, bv1, off);
        oi = __shfl_xor_sync(FULLMASK, bi1, off);
        if (ov > bv1 || (ov == bv1 && oi < bi1)) { bv1 = ov; bi1 = oi; }
    }
    if (lane == 0) {
        redv[0][wid] = bv0; redi[0][wid] = bi0;
        redv[1][wid] = bv1; redi[1][wid] = bi1;
    }
    __syncthreads();
    if (tid < SBT) {
        uint32_t v = redv[tid][0], i = redi[tid][0];
        #pragma unroll
        for (int w = 1; w < 8; w++) {
            uint32_t ov = redv[tid][w], oi = redi[tid][w];
            if (ov > v || (ov == v && oi < i)) { v = ov; i = oi; }
        }
        if (s0 + tid < tbg) d_lab[b][i] = 0;
    }
}

// Pass 5: emit labels (as float) + bbox regression targets.
__global__ __launch_bounds__(256) void k_out(const float4* __restrict__ boxes,
                                             const float4* __restrict__ gt,
                                             float* __restrict__ outL,
                                             float4* __restrict__ outB) {
    __shared__ float4 sgt[NG];
    int b = blockIdx.y, tid = threadIdx.x;
    if (tid < NG) sgt[tid] = gt[b * NG + tid];
    __syncthreads();
    int i = blockIdx.x * 256 + tid;
    int lab = d_lab[b][i];
    outL[b * N_ANCH + i] = (float)lab;
    float4 t = make_float4(0.f, 0.f, 0.f, 0.f);
    if (lab > 0) {
        float4 a = boxes[i];
        float4 g = sgt[d_aidx[b][i]];
        float ew = a.z - a.x + 1.0f, eh = a.w - a.y + 1.0f;
        float ecx = a.x + 0.5f * ew, ecy = a.y + 0.5f * eh;
        float gw = g.z - g.x + 1.0f, gh = g.w - g.y + 1.0f;
        float gcx = g.x + 0.5f * gw, gcy = g.y + 0.5f * gh;
        t.x = (gcx - ecx) / ew;
        t.y = (gcy - ecy) / eh;
        t.z = logf(gw / ew);
        t.w = logf(gh / eh);
    }
    outB[b * N_ANCH + i] = t;
}

// ---------------------------------------------------------------------------
extern "C" void kernel_launch(void* const* d_in, const int* in_sizes, int n_in,
                              void* d_out, int out_size) {
    const float4* boxes = (const float4*)d_in[0];
    const float4* gt    = (const float4*)d_in[1];
    const int*    gti   = (const int*)d_in[3];   // gt_ignore_labels
    const float*  imi   = (const float*)d_in[4]; // im_info
    float* out = (float*)d_out;

    // Host-side key derivation (jax.random.key(42), partitionable threefry).
    Keys keys;
    for (int b = 0; b < NB; b++) {
        uint32_t kb0, kb1;
        threefry(0u, 42u, 0u, (uint32_t)b, kb0, kb1);         // split(key,B)[b]
        threefry(kb0, kb1, 0u, 0u, keys.kp0[b], keys.kp1[b]); // kp
        threefry(kb0, kb1, 0u, 1u, keys.kn0[b], keys.kn1[b]); // kn
    }

    k_init<<<1, 256>>>();
    k_bins<<<NB, 256>>>(gt, gti);
    k_colmax<<<dim3(N_ANCH / 1024, NB), 256>>>(boxes, gt, imi);
    k_match<<<dim3(N_ANCH / 1024, NB), 256>>>(boxes, gt, imi, keys);
    k_select<<<NB, 1024>>>();
    k_sample<<<dim3(SB / SBT, NB), 256>>>(keys);
    k_out<<<dim3(N_ANCH / 256, NB), 256>>>(boxes, gt, out,
                                           (float4*)(out + NB * N_ANCH));
}

// round 7
// speedup vs baseline: 1.7426x; 1.0853x over previous
#include <cuda_runtime.h>
#include <cstdint>

// ============================================================================
// RPN GT matcher — bit-exact JAX Threefry (partitionable), integer-monotone
// gumbel/uniform ordering, GT spatial binning.
// R4 (resubmit; R5 bench was an infra failure): sampler Threefry adds forced
// onto the FMA pipe via opaque *one multiplier (IMAD), relieving the
// saturated ALU pipe (SHF/LOP3).
// ============================================================================

#define N_ANCH 262144
#define NB 4
#define NG 64
#define TFG 153          // TARGET_FG
#define SB 512           // SAMPLE_BATCH
#define SBT 2            // samples per block in k_sample
#define FULLMASK 0xFFFFFFFFu
#define NCELL 256        // 16x16 cells of 64px

struct Keys { uint32_t kp0[NB], kp1[NB], kn0[NB], kn1[NB]; uint32_t one; };

__host__ __device__ __forceinline__ uint32_t rotl32(uint32_t x, int r) {
#ifdef __CUDA_ARCH__
    return __funnelshift_l(x, x, r);
#else
    return (x << r) | (x >> (32 - r));
#endif
}

// Threefry-2x32, 20 rounds, exactly as jax._src.prng.threefry2x32 (host/ref)
__host__ __device__ __forceinline__ void threefry(uint32_t k0, uint32_t k1,
                                                  uint32_t x0, uint32_t x1,
                                                  uint32_t& o0, uint32_t& o1) {
    uint32_t ks2 = k0 ^ k1 ^ 0x1BD11BDAu;
    x0 += k0; x1 += k1;
#define TFR(r) { x0 += x1; x1 = rotl32(x1, r); x1 ^= x0; }
    TFR(13) TFR(15) TFR(26) TFR(6)
    x0 += k1;  x1 += ks2 + 1u;
    TFR(17) TFR(29) TFR(16) TFR(24)
    x0 += ks2; x1 += k0 + 2u;
    TFR(13) TFR(15) TFR(26) TFR(6)
    x0 += k0;  x1 += k1 + 3u;
    TFR(17) TFR(29) TFR(16) TFR(24)
    x0 += k1;  x1 += ks2 + 4u;
    TFR(13) TFR(15) TFR(26) TFR(6)
    x0 += ks2; x1 += k0 + 5u;
#undef TFR
    o0 = x0; o1 = x1;
}

// Threefry with all adds expressed as a*one+b (one==1 at runtime, opaque to
// the compiler) so ptxas emits IMAD on the fma pipe instead of IADD3 on the
// saturated alu pipe. x1 must be passed pre-added with k1 (counter x0 = 0).
// Returns o0 ^ o1 (partitionable 32-bit output).
__device__ __forceinline__ uint32_t tf_imad(uint32_t k0, uint32_t k1,
                                            uint32_t ks2,
                                            uint32_t kA, uint32_t kB,
                                            uint32_t kC, uint32_t kD,
                                            uint32_t kE,
                                            uint32_t x1, uint32_t one) {
    uint32_t x0 = k0;
#define AD(a, b) ((a) * one + (b))
#define RR(r) { x0 = AD(x0, x1); x1 = rotl32(x1, (r)); x1 ^= x0; }
    RR(13) RR(15) RR(26) RR(6)
    x0 = AD(x0, k1);  x1 = AD(x1, kA);
    RR(17) RR(29) RR(16) RR(24)
    x0 = AD(x0, ks2); x1 = AD(x1, kB);
    RR(13) RR(15) RR(26) RR(6)
    x0 = AD(x0, k0);  x1 = AD(x1, kC);
    RR(17) RR(29) RR(16) RR(24)
    x0 = AD(x0, k1);  x1 = AD(x1, kD);
    RR(13) RR(15) RR(26) RR(6)
    return AD(x0, ks2) ^ AD(x1, kE);
#undef AD
#undef RR
}

// ---------------------------------------------------------------------------
__device__ __forceinline__ float f_area(float4 v) {
    return __fmul_rn(__fadd_rn(__fsub_rn(v.z, v.x), 1.0f),
                     __fadd_rn(__fsub_rn(v.w, v.y), 1.0f));
}

// ---------------------------------------------------------------------------
// Scratch (static __device__ — no allocation allowed)
// ---------------------------------------------------------------------------
__device__ uint32_t d_g2a[NB][NG];
__device__ uint8_t  d_aidx[NB][N_ANCH];
__device__ int8_t   d_lab[NB][N_ANCH];
__device__ unsigned long long d_poskey[NB][N_ANCH];
__device__ int      d_negl[NB][N_ANCH];
__device__ int      d_poscnt[NB], d_negcnt[NB], d_tbg[NB], d_dosamp[NB];
__device__ __align__(16) uint8_t d_cellgt[NB][NCELL][64];
__device__ int      d_cellcnt[NB][NCELL];

// ---------------------------------------------------------------------------
__global__ __launch_bounds__(256) void k_init() {
    int t = threadIdx.x;
    if (t < NB * NG) ((uint32_t*)d_g2a)[t] = 0;
    if (t < NB) { d_poscnt[t] = 0; d_negcnt[t] = 0; }
}

// Bin valid GTs into 16x16 cells keyed by anchor (x1,y1) position.
__global__ __launch_bounds__(256) void k_bins(const float4* __restrict__ gt,
                                              const int* __restrict__ gti) {
    int t = blockIdx.x * 256 + threadIdx.x;
    int b = t >> 8, c = t & 255;
    int cx = c & 15, cy = c >> 4;
    float x0 = cx * 64.0f, y0 = cy * 64.0f;
    int n = 0;
    for (int g = 0; g < NG; g++) {
        if (gti[b * NG + g] != 0) continue;
        float4 gb = gt[b * NG + g];
        bool ox = (gb.z >= x0 - 1.5f) && (gb.x <= x0 + 226.5f);
        bool oy = (gb.w >= y0 - 1.5f) && (gb.y <= y0 + 226.5f);
        if (ox && oy) d_cellgt[b][c][n++] = (uint8_t)g;
    }
    d_cellcnt[b][c] = n;
}

// Pass 1: per-gt column max (binned; divide only when inter>0).
__global__ __launch_bounds__(256) void k_colmax(const float4* __restrict__ boxes,
                                                const float4* __restrict__ gt,
                                                const float* __restrict__ imi) {
    __shared__ float4 sgt[NG];
    __shared__ float  sga[NG];
    __shared__ uint32_t sg2a[NG];
    __shared__ uint8_t slist[NCELL * 64];
    __shared__ int     scnt[NCELL];
    int b = blockIdx.y, tid = threadIdx.x;
    if (tid < NG) {
        sg2a[tid] = 0;
        float4 g = gt[b * NG + tid];
        sgt[tid] = g; sga[tid] = f_area(g);
    }
    {
        const int4* src = (const int4*)d_cellgt[b];
        int4* dst = (int4*)slist;
        for (int k = tid; k < NCELL * 64 / 16; k += 256) dst[k] = src[k];
        scnt[tid] = d_cellcnt[b][tid];
    }
    __syncthreads();
    float limw = __fadd_rn(imi[b * 3 + 1], 1.0f);
    float limh = __fadd_rn(imi[b * 3 + 0], 1.0f);
    int base = blockIdx.x * 1024 + tid;
    for (int it = 0; it < 4; it++) {
        int i = base + it * 256;
        float4 a = boxes[i];
        bool inside = (a.x >= 0.0f) && (a.y >= 0.0f) && (a.z < limw) && (a.w < limh);
        if (!inside) continue;
        float aa = f_area(a);
        int cx = min((int)(a.x * (1.0f / 64.0f)), 15);
        int cy = min((int)(a.y * (1.0f / 64.0f)), 15);
        int c = cy * 16 + cx;
        int n = scnt[c];
        const uint8_t* lp = &slist[c * 64];
        for (int j = 0; j < n; j++) {
            int g = lp[j];
            float4 gb = sgt[g];
            float wx = __fadd_rn(__fsub_rn(fminf(a.z, gb.z), fmaxf(a.x, gb.x)), 1.0f);
            float wy = __fadd_rn(__fsub_rn(fminf(a.w, gb.w), fmaxf(a.y, gb.y)), 1.0f);
            wx = fmaxf(wx, 0.0f); wy = fmaxf(wy, 0.0f);
            float inter = __fmul_rn(wx, wy);
            if (inter > 0.0f) {
                float v = __fdiv_rn(inter, __fsub_rn(__fadd_rn(aa, sga[g]), inter));
                atomicMax(&sg2a[g], __float_as_uint(v));
            }
        }
    }
    __syncthreads();
    if (tid < NG && sg2a[tid]) atomicMax(&d_g2a[b][tid], sg2a[tid]);
}

// Pass 2: per-anchor match + classification + compaction + priority keys.
__global__ __launch_bounds__(256) void k_match(const float4* __restrict__ boxes,
                                               const float4* __restrict__ gt,
                                               const float* __restrict__ imi,
                                               Keys keys) {
    __shared__ float4 sgt[NG];
    __shared__ float  sga[NG], sg2af[NG];
    __shared__ uint8_t slist[NCELL * 64];
    __shared__ int     scnt[NCELL];
    int b = blockIdx.y, tid = threadIdx.x, lane = tid & 31;
    if (tid < NG) {
        float4 g = gt[b * NG + tid];
        sgt[tid] = g; sga[tid] = f_area(g);
        float f = __uint_as_float(d_g2a[b][tid]);
        sg2af[tid] = (f == 0.0f) ? 1.0f : f;
    }
    {
        const int4* src = (const int4*)d_cellgt[b];
        int4* dst = (int4*)slist;
        for (int k = tid; k < NCELL * 64 / 16; k += 256) dst[k] = src[k];
        scnt[tid] = d_cellcnt[b][tid];
    }
    __syncthreads();
    uint32_t pk0 = keys.kp0[b], pk1 = keys.kp1[b];
    uint32_t pks2 = pk0 ^ pk1 ^ 0x1BD11BDAu;
    float limw = __fadd_rn(imi[b * 3 + 1], 1.0f);
    float limh = __fadd_rn(imi[b * 3 + 0], 1.0f);
    int base = blockIdx.x * 1024 + tid;
    for (int it = 0; it < 4; it++) {
        int i = base + it * 256;
        float4 a = boxes[i];
        bool inside = (a.x >= 0.0f) && (a.y >= 0.0f) && (a.z < limw) && (a.w < limh);
        float best = 0.0f; int bidx = 0; bool wm = false;
        if (inside) {
            float aa = f_area(a);
            int cx = min((int)(a.x * (1.0f / 64.0f)), 15);
            int cy = min((int)(a.y * (1.0f / 64.0f)), 15);
            int c = cy * 16 + cx;
            int n = scnt[c];
            const uint8_t* lp = &slist[c * 64];
            for (int j = 0; j < n; j++) {
                int g = lp[j];
                float4 gb = sgt[g];
                float wx = __fadd_rn(__fsub_rn(fminf(a.z, gb.z), fmaxf(a.x, gb.x)), 1.0f);
                float wy = __fadd_rn(__fsub_rn(fminf(a.w, gb.w), fmaxf(a.y, gb.y)), 1.0f);
                wx = fmaxf(wx, 0.0f); wy = fmaxf(wy, 0.0f);
                float inter = __fmul_rn(wx, wy);
                if (inter > 0.0f) {
                    float v = __fdiv_rn(inter, __fsub_rn(__fadd_rn(aa, sga[g]), inter));
                    if (v > best) { best = v; bidx = g; }
                    wm |= (v == sg2af[g]);
                }
            }
        }
        bool pos = inside && (wm || best >= 0.5f);
        bool neg = inside && (best < 0.3f);
        d_aidx[b][i] = (uint8_t)bidx;
        d_lab[b][i] = -1;

        unsigned mneg = __ballot_sync(FULLMASK, neg);
        if (mneg) {
            int leader = __ffs(mneg) - 1, basek = 0;
            if (lane == leader) basek = atomicAdd(&d_negcnt[b], __popc(mneg));
            basek = __shfl_sync(FULLMASK, basek, leader);
            if (neg) d_negl[b][basek + __popc(mneg & ((1u << lane) - 1))] = i;
        }
        unsigned mpos = __ballot_sync(FULLMASK, pos);
        if (mpos) {
            int leader = __ffs(mpos) - 1, basek = 0;
            if (lane == leader) basek = atomicAdd(&d_poscnt[b], __popc(mpos));
            basek = __shfl_sync(FULLMASK, basek, leader);
            if (pos) {
                uint32_t bits = tf_imad(pk0, pk1, pks2,
                                        pks2 + 1u, pk0 + 2u, pk1 + 3u,
                                        pks2 + 4u, pk0 + 5u,
                                        (uint32_t)i + pk1, keys.one);
                uint32_t m23 = bits >> 9;
                unsigned long long key =
                    ((unsigned long long)m23 << 18) | (unsigned)(N_ANCH - 1 - i);
                d_poskey[b][basek + __popc(mpos & ((1u << lane) - 1))] = key;
            }
        }
    }
}

// Pass 3: O(P) top-TFG selection via histogram + exact rank in threshold bin.
#define NBIN 4096
#define BINCAP 2048
__global__ __launch_bounds__(1024) void k_select() {
    __shared__ uint32_t hist[NBIN];
    __shared__ unsigned long long binkeys[BINCAP];
    __shared__ int s_thr, s_need, s_cnt;
    int b = blockIdx.x, tid = threadIdx.x;
    int P = d_poscnt[b];
    if (tid == 0) {
        int nf = min(P, TFG);
        int tb = SB - nf;
        d_tbg[b] = tb;
        d_dosamp[b] = (d_negcnt[b] > tb) ? 1 : 0;
    }
    if (P <= TFG) {
        for (int e = tid; e < P; e += 1024) {
            unsigned long long k = d_poskey[b][e];
            d_lab[b][N_ANCH - 1 - (int)(k & 0x3FFFFu)] = 1;
        }
        return;
    }
    for (int i = tid; i < NBIN; i += 1024) hist[i] = 0;
    __syncthreads();
    for (int e = tid; e < P; e += 1024)
        atomicAdd(&hist[(int)(d_poskey[b][e] >> 29)], 1u);
    __syncthreads();
    if (tid == 0) {
        int cum = 0, t = 0, need = TFG;
        for (int bin = NBIN - 1; bin >= 0; bin--) {
            int c = (int)hist[bin];
            if (cum + c >= TFG) { t = bin; need = TFG - cum; break; }
            cum += c;
        }
        s_thr = t; s_need = need; s_cnt = 0;
    }
    __syncthreads();
    int t = s_thr, need = s_need;
    for (int e = tid; e < P; e += 1024) {
        unsigned long long k = d_poskey[b][e];
        int bin = (int)(k >> 29);
        if (bin > t) {
            d_lab[b][N_ANCH - 1 - (int)(k & 0x3FFFFu)] = 1;
        } else if (bin == t) {
            int p = atomicAdd(&s_cnt, 1);
            if (p < BINCAP) binkeys[p] = k;
        }
    }
    __syncthreads();
    int C = min(s_cnt, BINCAP);
    for (int e = tid; e < C; e += 1024) {
        unsigned long long k = binkeys[e];
        int c = 0;
        for (int j = 0; j < C; j++) c += (binkeys[j] > k);
        if (c < need) d_lab[b][N_ANCH - 1 - (int)(k & 0x3FFFFu)] = 1;
    }
}

// Pass 4: categorical sampling. SBT samples per block; IMAD-balanced threefry;
// u32 masked-mantissa running max with rare tie branch; exact smallest-index
// tie-break through the reductions.
__global__ __launch_bounds__(256) void k_sample(Keys keys) {
    __shared__ uint32_t redv[SBT][8];
    __shared__ uint32_t redi[SBT][8];
    int b = blockIdx.y, tid = threadIdx.x;
    int s0 = blockIdx.x * SBT;
    int tbg = d_tbg[b];
    if (!d_dosamp[b] || s0 >= tbg) return;
    int M = d_negcnt[b];
    uint32_t one = keys.one;
    uint32_t k0 = keys.kn0[b], k1 = keys.kn1[b];
    uint32_t ks2 = k0 ^ k1 ^ 0x1BD11BDAu;
    uint32_t kA = ks2 + 1u, kB = k0 + 2u, kC = k1 + 3u, kD = ks2 + 4u, kE = k0 + 5u;
    uint32_t h0 = (uint32_t)s0 * (uint32_t)N_ANCH + k1;   // x1 base, sample s0
    uint32_t h1 = h0 + (uint32_t)N_ANCH;                  // sample s0+1

    uint32_t bv0 = 0, bi0 = 0xFFFFFFFFu, bv1 = 0, bi1 = 0xFFFFFFFFu;
    const int* negl = d_negl[b];
    for (int t = tid; t < M; t += 256) {
        uint32_t i = (uint32_t)__ldg(&negl[t]);
        uint32_t r0 = tf_imad(k0, k1, ks2, kA, kB, kC, kD, kE, h0 + i, one)
                      & 0xFFFFFE00u;
        if (r0 >= bv0) { if (r0 > bv0 || i < bi0) { bv0 = r0; bi0 = i; } }
        uint32_t r1 = tf_imad(k0, k1, ks2, kA, kB, kC, kD, kE, h1 + i, one)
                      & 0xFFFFFE00u;
        if (r1 >= bv1) { if (r1 > bv1 || i < bi1) { bv1 = r1; bi1 = i; } }
    }
    int lane = tid & 31, wid = tid >> 5;
    #pragma unroll
    for (int off = 16; off; off >>= 1) {
        uint32_t ov = __shfl_xor_sync(FULLMASK, bv0, off);
        uint32_t oi = __shfl_xor_sync(FULLMASK, bi0, off);
        if (ov > bv0 || (ov == bv0 && oi < bi0)) { bv0 = ov; bi0 = oi; }
        ov = __shfl_xor_sync(FULLMASK, bv1, off);
        oi = __shfl_xor_sync(FULLMASK, bi1, off);
        if (ov > bv1 || (ov == bv1 && oi < bi1)) { bv1 = ov; bi1 = oi; }
    }
    if (lane == 0) {
        redv[0][wid] = bv0; redi[0][wid] = bi0;
        redv[1][wid] = bv1; redi[1][wid] = bi1;
    }
    __syncthreads();
    if (tid < SBT) {
        uint32_t v = redv[tid][0], i = redi[tid][0];
        #pragma unroll
        for (int w = 1; w < 8; w++) {
            uint32_t ov = redv[tid][w], oi = redi[tid][w];
            if (ov > v || (ov == v && oi < i)) { v = ov; i = oi; }
        }
        if (s0 + tid < tbg) d_lab[b][i] = 0;
    }
}

// Pass 5: emit labels (as float) + bbox regression targets.
__global__ __launch_bounds__(256) void k_out(const float4* __restrict__ boxes,
                                             const float4* __restrict__ gt,
                                             float* __restrict__ outL,
                                             float4* __restrict__ outB) {
    __shared__ float4 sgt[NG];
    int b = blockIdx.y, tid = threadIdx.x;
    if (tid < NG) sgt[tid] = gt[b * NG + tid];
    __syncthreads();
    int i = blockIdx.x * 256 + tid;
    int lab = d_lab[b][i];
    outL[b * N_ANCH + i] = (float)lab;
    float4 t = make_float4(0.f, 0.f, 0.f, 0.f);
    if (lab > 0) {
        float4 a = boxes[i];
        float4 g = sgt[d_aidx[b][i]];
        float ew = a.z - a.x + 1.0f, eh = a.w - a.y + 1.0f;
        float ecx = a.x + 0.5f * ew, ecy = a.y + 0.5f * eh;
        float gw = g.z - g.x + 1.0f, gh = g.w - g.y + 1.0f;
        float gcx = g.x + 0.5f * gw, gcy = g.y + 0.5f * gh;
        t.x = (gcx - ecx) / ew;
        t.y = (gcy - ecy) / eh;
        t.z = logf(gw / ew);
        t.w = logf(gh / eh);
    }
    outB[b * N_ANCH + i] = t;
}

// ---------------------------------------------------------------------------
extern "C" void kernel_launch(void* const* d_in, const int* in_sizes, int n_in,
                              void* d_out, int out_size) {
    const float4* boxes = (const float4*)d_in[0];
    const float4* gt    = (const float4*)d_in[1];
    const int*    gti   = (const int*)d_in[3];   // gt_ignore_labels
    const float*  imi   = (const float*)d_in[4]; // im_info
    float* out = (float*)d_out;

    // Host-side key derivation (jax.random.key(42), partitionable threefry).
    Keys keys;
    keys.one = 1u;
    for (int b = 0; b < NB; b++) {
        uint32_t kb0, kb1;
        threefry(0u, 42u, 0u, (uint32_t)b, kb0, kb1);         // split(key,B)[b]
        threefry(kb0, kb1, 0u, 0u, keys.kp0[b], keys.kp1[b]); // kp
        threefry(kb0, kb1, 0u, 1u, keys.kn0[b], keys.kn1[b]); // kn
    }

    k_init<<<1, 256>>>();
    k_bins<<<NB, 256>>>(gt, gti);
    k_colmax<<<dim3(N_ANCH / 1024, NB), 256>>>(boxes, gt, imi);
    k_match<<<dim3(N_ANCH / 1024, NB), 256>>>(boxes, gt, imi, keys);
    k_select<<<NB, 1024>>>();
    k_sample<<<dim3(SB / SBT, NB), 256>>>(keys);
    k_out<<<dim3(N_ANCH / 256, NB), 256>>>(boxes, gt, out,
                                           (float4*)(out + NB * N_ANCH));
}